// round 10
// baseline (speedup 1.0000x reference)
#include <cuda_runtime.h>
#include <cstdint>

// Problem constants (fixed shapes per reference)
constexpr int B_ = 8;
constexpr int S_ = 4096;
constexpr int D_ = 2048;
constexpr int R_ = 4;
// Effective math: out[b,s,:] = relu(0.25 * (x[b,s,:] @ Bc_b) @ Ac_b),
// Bc_b = concat(adapter_b[4b..4b+3]) -> [2048,16], Ac_b -> [16,2048].

// ---- Stage 1 config ----
constexpr int S1_THREADS = 256;
constexpr int S1_ROWS = 128;        // rows per block
constexpr int KSLAB = 64;           // k per smem tile
constexpr int NTILES = D_ / KSLAB;  // 32
constexpr int XS_STR = 65;          // xs row stride (odd -> conflict-free)
constexpr int BS_STR = 20;          // bs row stride (16B-aligned LDS.128)

// ---- Stage 2 config ----
constexpr int SROWS = 64;
constexpr int S2_THREADS = 256;

// h: [row][16], 2 MB -> L2-resident
__device__ float g_h[(size_t)B_ * S_ * 16];

// ---- packed f32x2 helpers (sm_100+ PTX) ----
__device__ __forceinline__ unsigned long long fma2(unsigned long long a,
                                                   unsigned long long b,
                                                   unsigned long long c) {
    unsigned long long d;
    asm("fma.rn.f32x2 %0, %1, %2, %3;" : "=l"(d) : "l"(a), "l"(b), "l"(c));
    return d;
}
__device__ __forceinline__ unsigned long long add2(unsigned long long a,
                                                   unsigned long long b) {
    unsigned long long d;
    asm("add.rn.f32x2 %0, %1, %2;" : "=l"(d) : "l"(a), "l"(b));
    return d;
}
__device__ __forceinline__ unsigned long long pack2(float lo, float hi) {
    unsigned long long d;
    asm("mov.b64 %0, {%1, %2};" : "=l"(d) : "f"(lo), "f"(hi));
    return d;
}
__device__ __forceinline__ float2 unpack2(unsigned long long v) {
    float2 r;
    asm("mov.b64 {%0, %1}, %2;" : "=f"(r.x), "=f"(r.y) : "l"(v));
    return r;
}

// ============================================================================
// Stage 1: h[row][c] = sum_k x[row][k] * Bc[k][c]
// 256 threads = 8 warps; warp w owns k-stripe k ≡ w (mod 8) within each slab.
// Lane (cp = lane>>4, rg = lane&15) owns cols cp*8..+7 and 8 rows rg+16m.
// Per k per warp: 2 broadcast LDS.128 (B, amortized over 8 rows) +
// 8 conflict-free scalar LDS.32 (x) feed 32 fma2.
// 8-way cross-warp k reduction in smem (write / add2 / 4-way sum).
// ============================================================================
__global__ __launch_bounds__(S1_THREADS, 2) void lora_stage1(
    const float* __restrict__ x, const float* __restrict__ ab) {
    __shared__ float xs[S1_ROWS * XS_STR];  // 33.3 KB (reused as reduce buf)
    __shared__ float bs[KSLAB * BS_STR];    // 5.1 KB

    const int tid = threadIdx.x;
    const int w = tid >> 5;          // k-stripe 0..7
    const int lane = tid & 31;
    const int cp = lane >> 4;        // col half 0..1
    const int rg = lane & 15;        // row slot
    const int row0 = blockIdx.x * S1_ROWS;
    const int b = blockIdx.x >> 5;   // row0 / S_

    const float* bbase = ab + (size_t)(4 * b) * D_ * R_;
    const int bj = tid & 3;   // adapter slot for B loads
    const int bk = tid >> 2;  // k for B loads (0..63)

    unsigned long long acc[8][4];
#pragma unroll
    for (int m = 0; m < 8; m++)
#pragma unroll
        for (int c = 0; c < 4; c++) acc[m][c] = 0ull;

    // ---- prefetch tile 0 ----
    float4 xv[8];
    float4 bv;
    {
#pragma unroll
        for (int i = 0; i < 8; i++) {
            const int id = tid + i * 256;
            const int r = id >> 4;
            const int k4 = id & 15;
            xv[i] = *(const float4*)(x + (size_t)(row0 + r) * D_ + k4 * 4);
        }
        bv = *(const float4*)(bbase + (size_t)bj * (D_ * R_) + (size_t)bk * R_);
    }

    for (int t = 0; t < NTILES; t++) {
        __syncthreads();  // previous tile's compute done
        // store prefetched tile to smem
#pragma unroll
        for (int i = 0; i < 8; i++) {
            const int id = tid + i * 256;
            const int r = id >> 4;
            const int k4 = id & 15;
            float* p = &xs[r * XS_STR + k4 * 4];
            p[0] = xv[i].x; p[1] = xv[i].y; p[2] = xv[i].z; p[3] = xv[i].w;
        }
        *(float4*)&bs[bk * BS_STR + bj * 4] = bv;
        __syncthreads();

        // prefetch next tile while computing this one
        if (t + 1 < NTILES) {
            const int kb = (t + 1) * KSLAB;
#pragma unroll
            for (int i = 0; i < 8; i++) {
                const int id = tid + i * 256;
                const int r = id >> 4;
                const int k4 = id & 15;
                xv[i] = *(const float4*)(x + (size_t)(row0 + r) * D_ + kb +
                                         k4 * 4);
            }
            bv = *(const float4*)(bbase + (size_t)bj * (D_ * R_) +
                                  (size_t)(kb + bk) * R_);
        }

        // compute: my k-stripe (8 k), 8 rows, 8 cols
        const float* xr = &xs[rg * XS_STR];
#pragma unroll
        for (int step = 0; step < 8; step++) {
            const int k = w + step * 8;
            const ulonglong2* bp = (const ulonglong2*)&bs[k * BS_STR + cp * 8];
            const ulonglong2 bA = bp[0];  // cols cp*8 .. +3
            const ulonglong2 bB = bp[1];  // cols cp*8+4 .. +7
#pragma unroll
            for (int m = 0; m < 8; m++) {
                const float xf = xr[m * 16 * XS_STR + k];
                const unsigned long long p = pack2(xf, xf);
                acc[m][0] = fma2(p, bA.x, acc[m][0]);
                acc[m][1] = fma2(p, bA.y, acc[m][1]);
                acc[m][2] = fma2(p, bB.x, acc[m][2]);
                acc[m][3] = fma2(p, bB.y, acc[m][3]);
            }
        }
    }

    // ---- 8-way cross-warp reduction via smem (reuse xs: 4*128*16 = 8192) ----
    __syncthreads();
    float* red = xs;  // red[(q*128 + row)*16 + col], q = w&3
    {
        const int q = w & 3;
        if (w < 4) {
#pragma unroll
            for (int m = 0; m < 8; m++) {
                ulonglong2* p = (ulonglong2*)&red[(q * 128 + rg + 16 * m) * 16 +
                                                  cp * 8];
                p[0] = make_ulonglong2(acc[m][0], acc[m][1]);
                p[1] = make_ulonglong2(acc[m][2], acc[m][3]);
            }
        }
        __syncthreads();
        if (w >= 4) {
#pragma unroll
            for (int m = 0; m < 8; m++) {
                ulonglong2* p = (ulonglong2*)&red[(q * 128 + rg + 16 * m) * 16 +
                                                  cp * 8];
                ulonglong2 v0 = p[0];
                ulonglong2 v1 = p[1];
                p[0] = make_ulonglong2(add2(v0.x, acc[m][0]),
                                       add2(v0.y, acc[m][1]));
                p[1] = make_ulonglong2(add2(v1.x, acc[m][2]),
                                       add2(v1.y, acc[m][3]));
            }
        }
    }
    __syncthreads();

    {
        const int row = tid >> 1;
        const int coff = (tid & 1) * 8;
        float4 sa = make_float4(0.f, 0.f, 0.f, 0.f);
        float4 sb = make_float4(0.f, 0.f, 0.f, 0.f);
#pragma unroll
        for (int qq = 0; qq < 4; qq++) {
            const float* p = &red[(qq * 128 + row) * 16 + coff];
            float4 va = *(const float4*)(p + 0);
            float4 vb = *(const float4*)(p + 4);
            sa.x += va.x; sa.y += va.y; sa.z += va.z; sa.w += va.w;
            sb.x += vb.x; sb.y += vb.y; sb.z += vb.z; sb.w += vb.w;
        }
        float* o = g_h + (size_t)(row0 + row) * 16 + coff;
        *(float4*)(o + 0) = sa;
        *(float4*)(o + 4) = sb;
    }
}

// ============================================================================
// Stage 2: out[row][d] = relu( 0.25 * sum_c h[row][c] * Ac[c][d] )
// 256 threads; thread owns 8 d: {tid*4..+3} and {1024+tid*4..+3} -> block
// covers the FULL D=2048 for 64 rows. Per rr per warp: 16 scalar h-LDS
// (broadcast, 1 wf each) feed 64 fma2. A slice (16x8) in registers.
// ============================================================================
__global__ __launch_bounds__(S2_THREADS, 2) void lora_stage2(
    const float* __restrict__ aa, float* __restrict__ out) {
    __shared__ float hsf[SROWS * 16];  // 0.25*h scalars, 4KB

    const int tid = threadIdx.x;
    const int b = blockIdx.y;
    const int s0 = blockIdx.x * SROWS;
    const size_t row0 = (size_t)b * S_ + s0;
    const int d0 = tid * 4;  // second block at d0 + 1024

    // Fill hsf: 1024 floats, one float4 per thread, scale by 0.25
    {
        const float4* hp = (const float4*)(g_h + row0 * 16);
        float4 v = hp[tid];
        float* o = &hsf[tid * 4];
        o[0] = v.x * 0.25f;
        o[1] = v.y * 0.25f;
        o[2] = v.z * 0.25f;
        o[3] = v.w * 0.25f;
    }
    __syncthreads();

    // A slice into registers: 16 c x 8 d -> 16 x 4 f32x2
    unsigned long long areg[16][4];
#pragma unroll
    for (int j = 0; j < 4; j++) {
#pragma unroll
        for (int r = 0; r < 4; r++) {
            const float* base =
                aa + (size_t)(4 * b + j) * (R_ * D_) + (size_t)r * D_;
            float4 v0 = *(const float4*)(base + d0);
            float4 v1 = *(const float4*)(base + d0 + 1024);
            areg[j * 4 + r][0] = pack2(v0.x, v0.y);
            areg[j * 4 + r][1] = pack2(v0.z, v0.w);
            areg[j * 4 + r][2] = pack2(v1.x, v1.y);
            areg[j * 4 + r][3] = pack2(v1.z, v1.w);
        }
    }

    float* orow = out + row0 * D_ + d0;
    for (int rr = 0; rr < SROWS; rr++) {
        const float* hrow = &hsf[rr * 16];
        unsigned long long a0 = 0ull, a1 = 0ull, a2 = 0ull, a3 = 0ull;
        unsigned long long a4 = 0ull, a5 = 0ull, a6 = 0ull, a7 = 0ull;
#pragma unroll
        for (int c = 0; c < 16; c += 2) {
            const float h0 = hrow[c];
            const float h1 = hrow[c + 1];
            const unsigned long long hp0 = pack2(h0, h0);
            const unsigned long long hp1 = pack2(h1, h1);
            a0 = fma2(hp0, areg[c + 0][0], a0);
            a1 = fma2(hp0, areg[c + 0][1], a1);
            a2 = fma2(hp0, areg[c + 0][2], a2);
            a3 = fma2(hp0, areg[c + 0][3], a3);
            a4 = fma2(hp1, areg[c + 1][0], a4);
            a5 = fma2(hp1, areg[c + 1][1], a5);
            a6 = fma2(hp1, areg[c + 1][2], a6);
            a7 = fma2(hp1, areg[c + 1][3], a7);
        }
        const unsigned long long s0 = add2(a0, a4);
        const unsigned long long s1 = add2(a1, a5);
        const unsigned long long s2 = add2(a2, a6);
        const unsigned long long s3 = add2(a3, a7);
        float2 v0 = unpack2(s0);
        float2 v1 = unpack2(s1);
        float2 v2 = unpack2(s2);
        float2 v3 = unpack2(s3);
        float4 oA, oB;
        oA.x = fmaxf(v0.x, 0.0f);
        oA.y = fmaxf(v0.y, 0.0f);
        oA.z = fmaxf(v1.x, 0.0f);
        oA.w = fmaxf(v1.y, 0.0f);
        oB.x = fmaxf(v2.x, 0.0f);
        oB.y = fmaxf(v2.y, 0.0f);
        oB.z = fmaxf(v3.x, 0.0f);
        oB.w = fmaxf(v3.y, 0.0f);
        float* p = orow + (size_t)rr * D_;
        *(float4*)(p + 0) = oA;
        *(float4*)(p + 1024) = oB;
    }
}

extern "C" void kernel_launch(void* const* d_in, const int* in_sizes, int n_in,
                              void* d_out, int out_size) {
    const float* x = (const float*)d_in[0];
    const float* ab = (const float*)d_in[1];
    const float* aa = (const float*)d_in[2];
    float* out = (float*)d_out;

    lora_stage1<<<(B_ * S_) / S1_ROWS, S1_THREADS>>>(x, ab);  // 256 blocks

    dim3 g2(S_ / SROWS, B_);  // (64, 8) = 512 blocks, full D per block
    lora_stage2<<<g2, S2_THREADS>>>(aa, out);
}

// round 11
// speedup vs baseline: 1.1985x; 1.1985x over previous
#include <cuda_runtime.h>
#include <cstdint>

// Problem constants (fixed shapes per reference)
constexpr int B_ = 8;
constexpr int S_ = 4096;
constexpr int D_ = 2048;
constexpr int R_ = 4;
// Effective math: out[b,s,:] = relu(0.25 * (x[b,s,:] @ Bc_b) @ Ac_b),
// Bc_b = concat(adapter_b[4b..4b+3]) -> [2048,16], Ac_b -> [16,2048].

// ---- Stage 1 config ----
constexpr int S1_THREADS = 256;
constexpr int S1_ROWS = 128;        // rows per block
constexpr int KSLAB = 32;           // k per smem tile (small -> xv[4] prefetch)
constexpr int NTILES = D_ / KSLAB;  // 64
constexpr int XS_STR = 33;          // xs row stride (odd -> conflict-free LDS.32)
constexpr int BS_STR = 20;          // bs row stride (16B-aligned LDS.128)

// ---- Stage 2 config ----
constexpr int SROWS = 64;
constexpr int S2_THREADS = 256;

// h: [row][16], 2 MB -> L2-resident
__device__ float g_h[(size_t)B_ * S_ * 16];

// ---- packed f32x2 helpers (sm_100+ PTX) ----
__device__ __forceinline__ unsigned long long fma2(unsigned long long a,
                                                   unsigned long long b,
                                                   unsigned long long c) {
    unsigned long long d;
    asm("fma.rn.f32x2 %0, %1, %2, %3;" : "=l"(d) : "l"(a), "l"(b), "l"(c));
    return d;
}
__device__ __forceinline__ unsigned long long add2(unsigned long long a,
                                                   unsigned long long b) {
    unsigned long long d;
    asm("add.rn.f32x2 %0, %1, %2;" : "=l"(d) : "l"(a), "l"(b));
    return d;
}
__device__ __forceinline__ unsigned long long pack2(float lo, float hi) {
    unsigned long long d;
    asm("mov.b64 %0, {%1, %2};" : "=l"(d) : "f"(lo), "f"(hi));
    return d;
}
__device__ __forceinline__ float2 unpack2(unsigned long long v) {
    float2 r;
    asm("mov.b64 {%0, %1}, %2;" : "=f"(r.x), "=f"(r.y) : "l"(v));
    return r;
}

// ============================================================================
// Stage 1: h[row][c] = sum_k x[row][k] * Bc[k][c]
// 256 threads = 8 warps; warp w owns k ≡ w (mod 8) within each 32-k slab
// (4 k-steps per warp per tile). Lane (cp = lane>>4, rg = lane&15) owns
// cols cp*8..+7 and 8 rows rg+16m. Per k per warp: 2 broadcast LDS.128 (B)
// + 8 conflict-free scalar LDS.32 (x) feed 32 fma2 -> wf:fma balanced.
// Register budget: acc 64 + xv 16 + misc ~15 < 128 (no spill at occ 2).
// 8-way cross-warp k reduction in a dedicated smem buffer.
// ============================================================================
__global__ __launch_bounds__(S1_THREADS, 2) void lora_stage1(
    const float* __restrict__ x, const float* __restrict__ ab) {
    __shared__ float xs[S1_ROWS * XS_STR];   // 16.9 KB
    __shared__ float bs[KSLAB * BS_STR];     // 2.6 KB
    __shared__ float red[4 * S1_ROWS * 16];  // 32 KB

    const int tid = threadIdx.x;
    const int w = tid >> 5;          // k-stripe 0..7
    const int lane = tid & 31;
    const int cp = lane >> 4;        // col half 0..1
    const int rg = lane & 15;        // row slot
    const int row0 = blockIdx.x * S1_ROWS;
    const int b = blockIdx.x >> 5;   // row0 / S_

    const float* bbase = ab + (size_t)(4 * b) * D_ * R_;
    const int bj = tid & 3;   // adapter slot for B loads
    const int bk = tid >> 2;  // k for B loads (0..63 -> only tid<128 used)

    unsigned long long acc[8][4];
#pragma unroll
    for (int m = 0; m < 8; m++)
#pragma unroll
        for (int c = 0; c < 4; c++) acc[m][c] = 0ull;

    // loader mapping: 1024 float4 per tile, 4 per thread
    const int lr = tid >> 3;       // base row (0..31), +32 per chunk
    const int lk4 = tid & 7;       // float4 slot within 32-k slab

    // ---- prefetch tile 0 ----
    float4 xv[4];
    float4 bv = make_float4(0.f, 0.f, 0.f, 0.f);
    {
#pragma unroll
        for (int i = 0; i < 4; i++) {
            xv[i] = *(const float4*)(x + (size_t)(row0 + lr + i * 32) * D_ +
                                     lk4 * 4);
        }
        if (tid < 128)
            bv = *(const float4*)(bbase + (size_t)bj * (D_ * R_) +
                                  (size_t)bk * R_);
    }

    for (int t = 0; t < NTILES; t++) {
        __syncthreads();  // previous tile's compute done
        // store prefetched tile to smem (scalar STS, conflict-free)
#pragma unroll
        for (int i = 0; i < 4; i++) {
            float* p = &xs[(lr + i * 32) * XS_STR + lk4 * 4];
            p[0] = xv[i].x; p[1] = xv[i].y; p[2] = xv[i].z; p[3] = xv[i].w;
        }
        if (tid < 128) *(float4*)&bs[bk * BS_STR + bj * 4] = bv;
        __syncthreads();

        // prefetch next tile while computing this one
        if (t + 1 < NTILES) {
            const int kb = (t + 1) * KSLAB;
#pragma unroll
            for (int i = 0; i < 4; i++) {
                xv[i] = *(const float4*)(x + (size_t)(row0 + lr + i * 32) * D_ +
                                         kb + lk4 * 4);
            }
            if (tid < 128)
                bv = *(const float4*)(bbase + (size_t)bj * (D_ * R_) +
                                      (size_t)(kb + bk) * R_);
        }

        // compute: my 4 k-steps, 8 rows, 8 cols
#pragma unroll
        for (int step = 0; step < 4; step++) {
            const int k = w + step * 8;
            const ulonglong2* bp = (const ulonglong2*)&bs[k * BS_STR + cp * 8];
            const ulonglong2 bA = bp[0];  // cols cp*8 .. +3
            const ulonglong2 bB = bp[1];  // cols cp*8+4 .. +7
            const float* xk = &xs[rg * XS_STR + k];
#pragma unroll
            for (int m = 0; m < 8; m++) {
                const float xf = xk[m * 16 * XS_STR];
                const unsigned long long p = pack2(xf, xf);
                acc[m][0] = fma2(p, bA.x, acc[m][0]);
                acc[m][1] = fma2(p, bA.y, acc[m][1]);
                acc[m][2] = fma2(p, bB.x, acc[m][2]);
                acc[m][3] = fma2(p, bB.y, acc[m][3]);
            }
        }
    }

    // ---- 8-way cross-warp reduction in red[] ----
    const int q = w & 3;
    if (w < 4) {
#pragma unroll
        for (int m = 0; m < 8; m++) {
            ulonglong2* p =
                (ulonglong2*)&red[(q * 128 + rg + 16 * m) * 16 + cp * 8];
            p[0] = make_ulonglong2(acc[m][0], acc[m][1]);
            p[1] = make_ulonglong2(acc[m][2], acc[m][3]);
        }
    }
    __syncthreads();
    if (w >= 4) {
#pragma unroll
        for (int m = 0; m < 8; m++) {
            ulonglong2* p =
                (ulonglong2*)&red[(q * 128 + rg + 16 * m) * 16 + cp * 8];
            ulonglong2 v0 = p[0];
            ulonglong2 v1 = p[1];
            p[0] = make_ulonglong2(add2(v0.x, acc[m][0]),
                                   add2(v0.y, acc[m][1]));
            p[1] = make_ulonglong2(add2(v1.x, acc[m][2]),
                                   add2(v1.y, acc[m][3]));
        }
    }
    __syncthreads();

    {
        const int row = tid >> 1;
        const int coff = (tid & 1) * 8;
        float4 sa = make_float4(0.f, 0.f, 0.f, 0.f);
        float4 sb = make_float4(0.f, 0.f, 0.f, 0.f);
#pragma unroll
        for (int qq = 0; qq < 4; qq++) {
            const float* p = &red[(qq * 128 + row) * 16 + coff];
            float4 va = *(const float4*)(p + 0);
            float4 vb = *(const float4*)(p + 4);
            sa.x += va.x; sa.y += va.y; sa.z += va.z; sa.w += va.w;
            sb.x += vb.x; sb.y += vb.y; sb.z += vb.z; sb.w += vb.w;
        }
        float* o = g_h + (size_t)(row0 + row) * 16 + coff;
        *(float4*)(o + 0) = sa;
        *(float4*)(o + 4) = sb;
    }
}

// ============================================================================
// Stage 2 (R9 structure + occupancy 3): out = relu(0.25 * h @ Ac)
// 256 threads, 4 d per thread (areg 16x2 u64 = 32 regs, fits 85-reg cap).
// h read as scalar LDS.32 broadcasts (1 wf each) + ALU pack2.
// ============================================================================
__global__ __launch_bounds__(S2_THREADS, 3) void lora_stage2(
    const float* __restrict__ aa, float* __restrict__ out) {
    __shared__ float hsf[SROWS * 16];  // 0.25*h scalars, 4KB

    const int tid = threadIdx.x;
    const int b = blockIdx.z;
    const int s0 = blockIdx.x * SROWS;
    const size_t row0 = (size_t)b * S_ + s0;
    const int d0 = blockIdx.y * 1024 + tid * 4;

    // Fill hsf: 1024 floats = one float4 per thread, scale by 0.25
    {
        const float4* hp = (const float4*)(g_h + row0 * 16);
        float4 v = hp[tid];
        float* o = &hsf[tid * 4];
        o[0] = v.x * 0.25f;
        o[1] = v.y * 0.25f;
        o[2] = v.z * 0.25f;
        o[3] = v.w * 0.25f;
    }
    __syncthreads();

    // A slice into registers: 16 c x 4 d -> 16 x 2 f32x2
    unsigned long long areg[16][2];
#pragma unroll
    for (int j = 0; j < 4; j++) {
#pragma unroll
        for (int r = 0; r < 4; r++) {
            float4 v = *(const float4*)(aa + (size_t)(4 * b + j) * (R_ * D_) +
                                        (size_t)r * D_ + d0);
            areg[j * 4 + r][0] = pack2(v.x, v.y);
            areg[j * 4 + r][1] = pack2(v.z, v.w);
        }
    }

    float* orow = out + row0 * D_ + d0;
    for (int rr = 0; rr < SROWS; rr++) {
        const float* hrow = &hsf[rr * 16];
        unsigned long long a0 = 0ull, a1 = 0ull, a2 = 0ull, a3 = 0ull;
#pragma unroll
        for (int c = 0; c < 16; c += 2) {
            const float h0 = hrow[c];
            const float h1 = hrow[c + 1];
            const unsigned long long hp0 = pack2(h0, h0);
            const unsigned long long hp1 = pack2(h1, h1);
            a0 = fma2(hp0, areg[c + 0][0], a0);
            a1 = fma2(hp0, areg[c + 0][1], a1);
            a2 = fma2(hp1, areg[c + 1][0], a2);
            a3 = fma2(hp1, areg[c + 1][1], a3);
        }
        const unsigned long long s01 = add2(a0, a2);
        const unsigned long long s23 = add2(a1, a3);
        float2 v0 = unpack2(s01);
        float2 v1 = unpack2(s23);
        float4 o;
        o.x = fmaxf(v0.x, 0.0f);
        o.y = fmaxf(v0.y, 0.0f);
        o.z = fmaxf(v1.x, 0.0f);
        o.w = fmaxf(v1.y, 0.0f);
        *(float4*)(orow + (size_t)rr * D_) = o;
    }
}

extern "C" void kernel_launch(void* const* d_in, const int* in_sizes, int n_in,
                              void* d_out, int out_size) {
    const float* x = (const float*)d_in[0];
    const float* ab = (const float*)d_in[1];
    const float* aa = (const float*)d_in[2];
    float* out = (float*)d_out;

    lora_stage1<<<(B_ * S_) / S1_ROWS, S1_THREADS>>>(x, ab);  // 256 blocks

    dim3 g2(S_ / SROWS, D_ / 1024, B_);  // (64, 2, 8) = 1024 blocks
    lora_stage2<<<g2, S2_THREADS>>>(aa, out);
}

// round 12
// speedup vs baseline: 1.6133x; 1.3461x over previous
#include <cuda_runtime.h>
#include <cstdint>

// Problem constants (fixed shapes per reference)
constexpr int B_ = 8;
constexpr int S_ = 4096;
constexpr int D_ = 2048;
constexpr int R_ = 4;
// Effective math: out[b,s,:] = relu(0.25 * (x[b,s,:] @ Bc_b) @ Ac_b),
// Bc_b = concat(adapter_b[4b..4b+3]) -> [2048,16], Ac_b -> [16,2048].

// ---- Stage 1 config ----
constexpr int S1_THREADS = 256;   // 8 warps = 2 col-halves x 4 row-groups
constexpr int S1_ROWS = 32;       // rows per block (4 row-groups x 8 rows)

// ---- Stage 2 config ----
constexpr int SROWS = 64;
constexpr int S2_THREADS = 256;

// h: [row][16], 2 MB -> L2-resident
__device__ float g_h[(size_t)B_ * S_ * 16];

// ---- packed f32x2 helpers (sm_100+ PTX) ----
__device__ __forceinline__ unsigned long long fma2(unsigned long long a,
                                                   unsigned long long b,
                                                   unsigned long long c) {
    unsigned long long d;
    asm("fma.rn.f32x2 %0, %1, %2, %3;" : "=l"(d) : "l"(a), "l"(b), "l"(c));
    return d;
}
__device__ __forceinline__ unsigned long long add2(unsigned long long a,
                                                   unsigned long long b) {
    unsigned long long d;
    asm("add.rn.f32x2 %0, %1, %2;" : "=l"(d) : "l"(a), "l"(b));
    return d;
}
__device__ __forceinline__ unsigned long long pack2(float lo, float hi) {
    unsigned long long d;
    asm("mov.b64 %0, {%1, %2};" : "=l"(d) : "f"(lo), "f"(hi));
    return d;
}
__device__ __forceinline__ float2 unpack2(unsigned long long v) {
    float2 r;
    asm("mov.b64 {%0, %1}, %2;" : "=f"(r.x), "=f"(r.y) : "l"(v));
    return r;
}

// ============================================================================
// Stage 1: h[row][c] = sum_k x[row][k] * Bc[k][c]
// NO smem, NO syncthreads. 8 warps; warp = (cg col-half, wr row-group) owns
// 8 rows x 8 cols; k split across lanes (lane handles k ≡ lane mod 32).
//   x: coalesced LDG.32 (lane <-> k), streamed from DRAM.
//   B: LDG.128 pairs from adapter_b (128 KB, L1-resident after warmup).
//   per 32-k chunk per warp: ~16 wf vs 16 fma-cyc -> both pipes ~balanced.
// Final: 5-step element-splitting shfl butterfly reduces over lanes; lane l
// ends owning output element l (row l>>2, col-pair l&3) -> one 8B store.
// ============================================================================
__global__ __launch_bounds__(S1_THREADS, 2) void lora_stage1(
    const float* __restrict__ x, const float* __restrict__ ab) {
    const int tid = threadIdx.x;
    const int w = tid >> 5;         // warp 0..7
    const int lane = tid & 31;
    const int cg = w & 1;           // col half (cols cg*8 .. +7)
    const int wr = w >> 1;          // row group (rows wr*8 .. +7)
    const int row0 = blockIdx.x * S1_ROWS;
    const int b = blockIdx.x >> 7;  // row0 / S_  (128 blocks per batch)

    // x base: row (row0 + wr*8), k = lane; row m at immediate offset m*D_
    const float* xb = x + (size_t)(row0 + wr * 8) * D_ + lane;
    // B bases: cols cg*8..+3 from adapter j0=2cg, +4..+7 from j0+1
    const float* bb0 =
        ab + (size_t)(4 * b + 2 * cg) * (D_ * R_) + (size_t)lane * R_;
    const float* bb1 = bb0 + D_ * R_;

    unsigned long long acc[32];  // [m*4 + c2]: row m, col-pair c2
#pragma unroll
    for (int i = 0; i < 32; i++) acc[i] = 0ull;

#pragma unroll 4
    for (int k0 = 0; k0 < D_; k0 += 32) {
        // B row for my k: 4 u64 = cols cg*8 .. cg*8+7 (16B-aligned)
        const ulonglong2 bA = *(const ulonglong2*)(bb0 + (size_t)k0 * R_);
        const ulonglong2 bB = *(const ulonglong2*)(bb1 + (size_t)k0 * R_);
        // x for my k, 8 rows
        float xv[8];
#pragma unroll
        for (int m = 0; m < 8; m++) xv[m] = xb[(size_t)m * D_ + k0];

#pragma unroll
        for (int m = 0; m < 8; m++) {
            const unsigned long long p = pack2(xv[m], xv[m]);
            acc[m * 4 + 0] = fma2(p, bA.x, acc[m * 4 + 0]);
            acc[m * 4 + 1] = fma2(p, bA.y, acc[m * 4 + 1]);
            acc[m * 4 + 2] = fma2(p, bB.x, acc[m * 4 + 2]);
            acc[m * 4 + 3] = fma2(p, bB.y, acc[m * 4 + 3]);
        }
    }

    // ---- element-splitting butterfly reduction over 32 lanes ----
    // After step 'off', each lane keeps 'off' elements; the kept window's
    // bit log2(off) equals the lane's bit -> lane l ends with element l.
#pragma unroll
    for (int off = 16; off >= 1; off >>= 1) {
        const bool up = (lane & off) != 0;
#pragma unroll
        for (int i = 0; i < off; i++) {
            const unsigned long long give = up ? acc[i] : acc[i + off];
            const unsigned long long recv =
                __shfl_xor_sync(0xffffffffu, give, off);
            const unsigned long long keep = up ? acc[i + off] : acc[i];
            acc[i] = add2(keep, recv);
        }
    }

    // lane l owns h[row0 + wr*8 + (l>>2)][cg*8 + (l&3)*2 .. +1]
    const int m = lane >> 2;
    const int c2 = lane & 3;
    *(unsigned long long*)(g_h + (size_t)(row0 + wr * 8 + m) * 16 + cg * 8 +
                           c2 * 2) = acc[0];
}

// ============================================================================
// Stage 2 (R9 winner, verbatim): out = relu(0.25 * h @ Ac)
// 256 threads, 4 d per thread (areg 16x2 u64); h read as scalar LDS.32
// broadcasts (1 wf each) + ALU pack2. No launch_bounds (regs ~100, occ 2).
// ============================================================================
__global__ __launch_bounds__(S2_THREADS) void lora_stage2(
    const float* __restrict__ aa, float* __restrict__ out) {
    __shared__ float hsf[SROWS * 16];  // 0.25*h scalars, 4KB

    const int tid = threadIdx.x;
    const int b = blockIdx.z;
    const int s0 = blockIdx.x * SROWS;
    const size_t row0 = (size_t)b * S_ + s0;
    const int d0 = blockIdx.y * 1024 + tid * 4;

    // Fill hsf: scale by 0.25
    {
        const float2* hp = (const float2*)g_h + row0 * 8;
#pragma unroll
        for (int g = 0; g < (SROWS * 8) / S2_THREADS; g++) {
            const int i = tid + g * S2_THREADS;
            float2 v = hp[i];
            hsf[2 * i + 0] = v.x * 0.25f;
            hsf[2 * i + 1] = v.y * 0.25f;
        }
    }
    __syncthreads();

    // A slice into registers: 16 c x 4 d -> 16 x 2 f32x2
    unsigned long long areg[16][2];
#pragma unroll
    for (int j = 0; j < 4; j++) {
#pragma unroll
        for (int r = 0; r < 4; r++) {
            float4 v = *(const float4*)(aa + (size_t)(4 * b + j) * (R_ * D_) +
                                        (size_t)r * D_ + d0);
            areg[j * 4 + r][0] = pack2(v.x, v.y);
            areg[j * 4 + r][1] = pack2(v.z, v.w);
        }
    }

    float* orow = out + row0 * D_ + d0;
    for (int rr = 0; rr < SROWS; rr++) {
        const float* hrow = &hsf[rr * 16];
        unsigned long long a0 = 0ull, a1 = 0ull, a2 = 0ull, a3 = 0ull;
#pragma unroll
        for (int c = 0; c < 16; c += 2) {
            const float h0 = hrow[c];
            const float h1 = hrow[c + 1];
            const unsigned long long hp0 = pack2(h0, h0);
            const unsigned long long hp1 = pack2(h1, h1);
            a0 = fma2(hp0, areg[c + 0][0], a0);
            a1 = fma2(hp0, areg[c + 0][1], a1);
            a2 = fma2(hp1, areg[c + 1][0], a2);
            a3 = fma2(hp1, areg[c + 1][1], a3);
        }
        const unsigned long long s01 = add2(a0, a2);
        const unsigned long long s23 = add2(a1, a3);
        float2 v0 = unpack2(s01);
        float2 v1 = unpack2(s23);
        float4 o;
        o.x = fmaxf(v0.x, 0.0f);
        o.y = fmaxf(v0.y, 0.0f);
        o.z = fmaxf(v1.x, 0.0f);
        o.w = fmaxf(v1.y, 0.0f);
        *(float4*)(orow + (size_t)rr * D_) = o;
    }
}

extern "C" void kernel_launch(void* const* d_in, const int* in_sizes, int n_in,
                              void* d_out, int out_size) {
    const float* x = (const float*)d_in[0];
    const float* ab = (const float*)d_in[1];
    const float* aa = (const float*)d_in[2];
    float* out = (float*)d_out;

    lora_stage1<<<(B_ * S_) / S1_ROWS, S1_THREADS>>>(x, ab);  // 1024 blocks

    dim3 g2(S_ / SROWS, D_ / 1024, B_);  // (64, 2, 8) = 1024 blocks
    lora_stage2<<<g2, S2_THREADS>>>(aa, out);
}

// round 14
// speedup vs baseline: 2.0719x; 1.2843x over previous
#include <cuda_runtime.h>
#include <cstdint>

// Problem constants
constexpr int B_ = 8;
constexpr int S_ = 4096;
constexpr int D_ = 2048;
constexpr int R_ = 4;
// Effective math: out[b,s,:] = relu(0.25 * (x[b,s,:] @ Bc_b) @ Ac_b),
// Bc_b = concat(adapter_b[4b..4b+3]) -> [2048,16], Ac_b -> [16,2048].

// ---- Stage 1 (mma.sync tf32) config ----
constexpr int S1_THREADS = 256;      // 8 warps x 16-row m-tiles = 128 rows
constexpr int TILE_M = 128;
constexpr int KSLAB = 64;
constexpr int NSLAB = D_ / KSLAB;    // 32
constexpr int XS_STR = 68;           // 68 % 32 == 4 -> A-frag LDS conflict-free
constexpr int BS_STR = 40;           // 40 % 32 == 8 -> B-frag LDS conflict-free
// dynamic smem (floats): xs[128*68] | bhi[64*40] | blo[64*40]
constexpr int XS_OFF = 0;
constexpr int BHI_OFF = TILE_M * XS_STR;            // 8704
constexpr int BLO_OFF = BHI_OFF + KSLAB * BS_STR;   // 11264
constexpr int SM_FLOATS = BLO_OFF + KSLAB * BS_STR; // 13824
constexpr int SM_BYTES = SM_FLOATS * 4;             // 55296

// ---- Stage 2 config ----
constexpr int SROWS = 64;
constexpr int S2_THREADS = 256;

// h: [row][16], 2 MB -> L2-resident
__device__ float g_h[(size_t)B_ * S_ * 16];

// ============================ helpers ============================
__device__ __forceinline__ float tf32r(float v) {
    uint32_t r;
    asm("cvt.rna.tf32.f32 %0, %1;" : "=r"(r) : "f"(v));
    return __uint_as_float(r);
}
__device__ __forceinline__ void mma_tf32(float c[4], uint32_t a0, uint32_t a1,
                                         uint32_t a2, uint32_t a3, uint32_t b0,
                                         uint32_t b1) {
    asm volatile(
        "mma.sync.aligned.m16n8k8.row.col.f32.tf32.tf32.f32 "
        "{%0,%1,%2,%3}, {%4,%5,%6,%7}, {%8,%9}, {%0,%1,%2,%3};"
        : "+f"(c[0]), "+f"(c[1]), "+f"(c[2]), "+f"(c[3])
        : "r"(a0), "r"(a1), "r"(a2), "r"(a3), "r"(b0), "r"(b1));
}
// ---- packed f32x2 helpers (stage 2) ----
__device__ __forceinline__ unsigned long long fma2(unsigned long long a,
                                                   unsigned long long b,
                                                   unsigned long long c) {
    unsigned long long d;
    asm("fma.rn.f32x2 %0, %1, %2, %3;" : "=l"(d) : "l"(a), "l"(b), "l"(c));
    return d;
}
__device__ __forceinline__ unsigned long long add2(unsigned long long a,
                                                   unsigned long long b) {
    unsigned long long d;
    asm("add.rn.f32x2 %0, %1, %2;" : "=l"(d) : "l"(a), "l"(b));
    return d;
}
__device__ __forceinline__ unsigned long long pack2(float lo, float hi) {
    unsigned long long d;
    asm("mov.b64 %0, {%1, %2};" : "=l"(d) : "f"(lo), "f"(hi));
    return d;
}
__device__ __forceinline__ float2 unpack2(unsigned long long v) {
    float2 r;
    asm("mov.b64 {%0, %1}, %2;" : "=f"(r.x), "=f"(r.y) : "l"(v));
    return r;
}

// ============================================================================
// Stage 1: h[row][c] = sum_k x[row][k] * Bc[k][c]  via mma.sync m16n8k8 tf32.
// x rounded once to tf32 (rna) during staging; B split hi+lo tf32 (2 passes
// into the same f32 accumulator) -> only error source is x rounding (~3e-4).
// Warp w owns rows w*16..+15; per slab: 8 k-steps x 2 n-tiles x 2 passes.
// A-frag and B-frag LDS are bank-permutation conflict-free by stride choice.
// ============================================================================
__global__ __launch_bounds__(S1_THREADS) void lora_stage1_mma(
    const float* __restrict__ x, const float* __restrict__ ab) {
    extern __shared__ float sm[];
    float* xs = sm + XS_OFF;
    float* bhi = sm + BHI_OFF;
    float* blo = sm + BLO_OFF;

    const int tid = threadIdx.x;
    const int w = tid >> 5;
    const int lane = tid & 31;
    const int g = lane >> 2;   // group row / n within tile
    const int tg = lane & 3;   // k sub-index
    const int row0 = blockIdx.x * TILE_M;
    const int b = blockIdx.x >> 5;  // 32 CTAs per batch

    // x loader: iter i covers float4 fidx = i*256+tid -> row fidx>>4, kq fidx&15
    // B loader: thread -> k = tid>>2 (0..63), adapter slot j = tid&3 (n-group)
    const int bk = tid >> 2;
    const int bj = tid & 3;
    const float* bsrc =
        ab + (size_t)(4 * b + bj) * (D_ * R_) + (size_t)bk * R_;

    float acc[2][4];
#pragma unroll
    for (int nt = 0; nt < 2; nt++)
#pragma unroll
        for (int i = 0; i < 4; i++) acc[nt][i] = 0.0f;

    // ---- prefetch slab 0 ----
    float4 xv[8];
    float4 bv;
#pragma unroll
    for (int i = 0; i < 8; i++) {
        const int f = i * 256 + tid;
        xv[i] = *(const float4*)(x + (size_t)(row0 + (f >> 4)) * D_ +
                                 (f & 15) * 4);
    }
    bv = *(const float4*)bsrc;

    for (int t = 0; t < NSLAB; t++) {
        __syncthreads();  // previous slab's compute done
        // ---- stage x (tf32-rounded) ----
#pragma unroll
        for (int i = 0; i < 8; i++) {
            const int f = i * 256 + tid;
            float* p = &xs[(f >> 4) * XS_STR + (f & 15) * 4];
            p[0] = tf32r(xv[i].x);
            p[1] = tf32r(xv[i].y);
            p[2] = tf32r(xv[i].z);
            p[3] = tf32r(xv[i].w);
        }
        // ---- stage B hi/lo: B[k][n] k-major, n = bj*4 + r ----
        {
            float h0 = tf32r(bv.x), h1 = tf32r(bv.y), h2 = tf32r(bv.z),
                  h3 = tf32r(bv.w);
            float* ph = &bhi[bk * BS_STR + bj * 4];
            float* pl = &blo[bk * BS_STR + bj * 4];
            ph[0] = h0; ph[1] = h1; ph[2] = h2; ph[3] = h3;
            pl[0] = tf32r(bv.x - h0);
            pl[1] = tf32r(bv.y - h1);
            pl[2] = tf32r(bv.z - h2);
            pl[3] = tf32r(bv.w - h3);
        }
        __syncthreads();

        // ---- prefetch slab t+1 ----
        if (t + 1 < NSLAB) {
            const int kb = (t + 1) * KSLAB;
#pragma unroll
            for (int i = 0; i < 8; i++) {
                const int f = i * 256 + tid;
                xv[i] = *(const float4*)(x + (size_t)(row0 + (f >> 4)) * D_ +
                                         kb + (f & 15) * 4);
            }
            bv = *(const float4*)(bsrc + (size_t)kb * R_);
        }

        // ---- compute: 8 k-steps of m16n8k8, 2 n-tiles, 2 passes ----
        const float* xw = &xs[w * 16 * XS_STR];
#pragma unroll
        for (int ks = 0; ks < 8; ks++) {
            const int k0 = ks * 8;
            const uint32_t a0 = __float_as_uint(xw[g * XS_STR + k0 + tg]);
            const uint32_t a1 = __float_as_uint(xw[(g + 8) * XS_STR + k0 + tg]);
            const uint32_t a2 = __float_as_uint(xw[g * XS_STR + k0 + tg + 4]);
            const uint32_t a3 =
                __float_as_uint(xw[(g + 8) * XS_STR + k0 + tg + 4]);
#pragma unroll
            for (int nt = 0; nt < 2; nt++) {
                const int n0 = nt * 8 + g;
                const uint32_t bh0 =
                    __float_as_uint(bhi[(k0 + tg) * BS_STR + n0]);
                const uint32_t bh1 =
                    __float_as_uint(bhi[(k0 + tg + 4) * BS_STR + n0]);
                mma_tf32(acc[nt], a0, a1, a2, a3, bh0, bh1);
                const uint32_t bl0 =
                    __float_as_uint(blo[(k0 + tg) * BS_STR + n0]);
                const uint32_t bl1 =
                    __float_as_uint(blo[(k0 + tg + 4) * BS_STR + n0]);
                mma_tf32(acc[nt], a0, a1, a2, a3, bl0, bl1);
            }
        }
    }

    // ---- store C frags: lane holds rows (g, g+8), cols nt*8 + 2tg..+1 ----
#pragma unroll
    for (int nt = 0; nt < 2; nt++) {
        const int col = nt * 8 + 2 * tg;
        float* o0 = g_h + (size_t)(row0 + w * 16 + g) * 16 + col;
        o0[0] = acc[nt][0];
        o0[1] = acc[nt][1];
        float* o1 = g_h + (size_t)(row0 + w * 16 + g + 8) * 16 + col;
        o1[0] = acc[nt][2];
        o1[1] = acc[nt][3];
    }
}

// ============================================================================
// Stage 2 (R9/R12 winner, verbatim): out = relu(0.25 * h @ Ac)
// ============================================================================
__global__ __launch_bounds__(S2_THREADS) void lora_stage2(
    const float* __restrict__ aa, float* __restrict__ out) {
    __shared__ float hsf[SROWS * 16];

    const int tid = threadIdx.x;
    const int b = blockIdx.z;
    const int s0 = blockIdx.x * SROWS;
    const size_t row0 = (size_t)b * S_ + s0;
    const int d0 = blockIdx.y * 1024 + tid * 4;

    {
        const float2* hp = (const float2*)g_h + row0 * 8;
#pragma unroll
        for (int g = 0; g < (SROWS * 8) / S2_THREADS; g++) {
            const int i = tid + g * S2_THREADS;
            float2 v = hp[i];
            hsf[2 * i + 0] = v.x * 0.25f;
            hsf[2 * i + 1] = v.y * 0.25f;
        }
    }
    __syncthreads();

    unsigned long long areg[16][2];
#pragma unroll
    for (int j = 0; j < 4; j++) {
#pragma unroll
        for (int r = 0; r < 4; r++) {
            float4 v = *(const float4*)(aa + (size_t)(4 * b + j) * (R_ * D_) +
                                        (size_t)r * D_ + d0);
            areg[j * 4 + r][0] = pack2(v.x, v.y);
            areg[j * 4 + r][1] = pack2(v.z, v.w);
        }
    }

    float* orow = out + row0 * D_ + d0;
    for (int rr = 0; rr < SROWS; rr++) {
        const float* hrow = &hsf[rr * 16];
        unsigned long long a0 = 0ull, a1 = 0ull, a2 = 0ull, a3 = 0ull;
#pragma unroll
        for (int c = 0; c < 16; c += 2) {
            const float h0 = hrow[c];
            const float h1 = hrow[c + 1];
            const unsigned long long hp0 = pack2(h0, h0);
            const unsigned long long hp1 = pack2(h1, h1);
            a0 = fma2(hp0, areg[c + 0][0], a0);
            a1 = fma2(hp0, areg[c + 0][1], a1);
            a2 = fma2(hp1, areg[c + 1][0], a2);
            a3 = fma2(hp1, areg[c + 1][1], a3);
        }
        const unsigned long long s01 = add2(a0, a2);
        const unsigned long long s23 = add2(a1, a3);
        float2 v0 = unpack2(s01);
        float2 v1 = unpack2(s23);
        float4 o;
        o.x = fmaxf(v0.x, 0.0f);
        o.y = fmaxf(v0.y, 0.0f);
        o.z = fmaxf(v1.x, 0.0f);
        o.w = fmaxf(v1.y, 0.0f);
        *(float4*)(orow + (size_t)rr * D_) = o;
    }
}

extern "C" void kernel_launch(void* const* d_in, const int* in_sizes, int n_in,
                              void* d_out, int out_size) {
    const float* x = (const float*)d_in[0];
    const float* ab = (const float*)d_in[1];
    const float* aa = (const float*)d_in[2];
    float* out = (float*)d_out;

    static bool attr_set = false;
    if (!attr_set) {
        cudaFuncSetAttribute(lora_stage1_mma,
                             cudaFuncAttributeMaxDynamicSharedMemorySize,
                             SM_BYTES);
        attr_set = true;
    }
    lora_stage1_mma<<<(B_ * S_) / TILE_M, S1_THREADS, SM_BYTES>>>(x, ab);

    dim3 g2(S_ / SROWS, D_ / 1024, B_);
    lora_stage2<<<g2, S2_THREADS>>>(aa, out);
}

// round 15
// speedup vs baseline: 2.2313x; 1.0769x over previous
#include <cuda_runtime.h>
#include <cstdint>

// Problem constants
constexpr int B_ = 8;
constexpr int S_ = 4096;
constexpr int D_ = 2048;
constexpr int R_ = 4;
// Effective math: out[b,s,:] = relu(0.25 * (x[b,s,:] @ Bc_b) @ Ac_b),
// Bc_b = concat(adapter_b[4b..4b+3]) -> [2048,16], Ac_b -> [16,2048].

// ---- Stage 1 (mma.sync bf16 m16n8k16) config ----
constexpr int S1_THREADS = 256;  // 8 warps x m16 tiles = 128 rows
constexpr int TILE_M = 128;
constexpr int KSLAB = 64;            // 32 bf16x2 pairs per row per slab
constexpr int NSLAB = D_ / KSLAB;    // 32
constexpr int XS_STR = 36;           // u32 stride; bank = (4*row + col) % 32
constexpr int BS_STR = 40;           // u32 stride; bank = (8*kp + n) % 32

// ---- Stage 2 config ----
constexpr int SROWS = 64;
constexpr int S2_THREADS = 256;

// h: [row][16], 2 MB -> L2-resident
__device__ float g_h[(size_t)B_ * S_ * 16];

// ============================ helpers ============================
// pack high-16 bits (bf16 truncation) of two floats: low half = a, high = b
__device__ __forceinline__ uint32_t bfpack_hi(float a, float b) {
    uint32_t r;
    asm("prmt.b32 %0, %1, %2, 0x7632;"
        : "=r"(r) : "r"(__float_as_uint(a)), "r"(__float_as_uint(b)));
    return r;
}
// round-to-nearest bf16x2 pack: low half = a, high = b
__device__ __forceinline__ uint32_t bfpack_rn(float a, float b) {
    uint32_t r;
    asm("cvt.rn.bf16x2.f32 %0, %1, %2;" : "=r"(r) : "f"(b), "f"(a));
    return r;
}
__device__ __forceinline__ float bflo_f(uint32_t p) {
    return __uint_as_float(p << 16);
}
__device__ __forceinline__ float bfhi_f(uint32_t p) {
    return __uint_as_float(p & 0xffff0000u);
}
__device__ __forceinline__ void mma_bf16(float c[4], uint32_t a0, uint32_t a1,
                                         uint32_t a2, uint32_t a3, uint32_t b0,
                                         uint32_t b1) {
    asm volatile(
        "mma.sync.aligned.m16n8k16.row.col.f32.bf16.bf16.f32 "
        "{%0,%1,%2,%3}, {%4,%5,%6,%7}, {%8,%9}, {%0,%1,%2,%3};"
        : "+f"(c[0]), "+f"(c[1]), "+f"(c[2]), "+f"(c[3])
        : "r"(a0), "r"(a1), "r"(a2), "r"(a3), "r"(b0), "r"(b1));
}
// ---- packed f32x2 helpers (stage 2) ----
__device__ __forceinline__ unsigned long long fma2(unsigned long long a,
                                                   unsigned long long b,
                                                   unsigned long long c) {
    unsigned long long d;
    asm("fma.rn.f32x2 %0, %1, %2, %3;" : "=l"(d) : "l"(a), "l"(b), "l"(c));
    return d;
}
__device__ __forceinline__ unsigned long long add2(unsigned long long a,
                                                   unsigned long long b) {
    unsigned long long d;
    asm("add.rn.f32x2 %0, %1, %2;" : "=l"(d) : "l"(a), "l"(b));
    return d;
}
__device__ __forceinline__ unsigned long long pack2(float lo, float hi) {
    unsigned long long d;
    asm("mov.b64 %0, {%1, %2};" : "=l"(d) : "f"(lo), "f"(hi));
    return d;
}
__device__ __forceinline__ float2 unpack2(unsigned long long v) {
    float2 r;
    asm("mov.b64 {%0, %1}, %2;" : "=f"(r.x), "=f"(r.y) : "l"(v));
    return r;
}

// ============================================================================
// Stage 1: h = X @ Bc via mma.sync m16n8k16 bf16, 3-pass hi/lo split:
//   x = xh + xl, B = bh + bl;  acc += xh*bh + xh*bl + xl*bh  (err ~2^-16)
// Warp w owns rows w*16..+15. Per 64-k slab: 4 k16-steps x 2 n-tiles x 3.
// xs: u32[row][36], pair p stored at col (p ^ (row&1)) -> STS and all A-frag
// LDS single-wavefront. bs: u32[kp][40] -> B-frag LDS conflict-free.
// ============================================================================
__global__ __launch_bounds__(S1_THREADS) void lora_stage1_mma(
    const float* __restrict__ x, const float* __restrict__ ab) {
    __shared__ uint32_t xh[TILE_M * XS_STR];  // 18432 B
    __shared__ uint32_t xl[TILE_M * XS_STR];  // 18432 B
    __shared__ uint32_t bh[32 * BS_STR];      // 5120 B
    __shared__ uint32_t bl[32 * BS_STR];      // 5120 B

    const int tid = threadIdx.x;
    const int w = tid >> 5;
    const int lane = tid & 31;
    const int g = lane >> 2;  // frag row / n
    const int tg = lane & 3;  // frag k sub-index
    const int row0 = blockIdx.x * TILE_M;
    const int b = blockIdx.x >> 5;  // 32 CTAs per batch

    // B loader mapping: thread -> (kp = t>>4 (+16/iter), n = t&15)
    const int bkp = tid >> 4;
    const int bn = tid & 15;
    const float* bsrc0 =
        ab + ((size_t)(4 * b + (bn >> 2)) * D_) * R_ + (bn & 3);

    float acc[2][4];
#pragma unroll
    for (int nt = 0; nt < 2; nt++)
#pragma unroll
        for (int i = 0; i < 4; i++) acc[nt][i] = 0.0f;

    // ---- prefetch slab 0 ----
    float4 xv[8];
    float be[2][2];
#pragma unroll
    for (int i = 0; i < 8; i++) {
        const int f = i * 256 + tid;
        xv[i] = *(const float4*)(x + (size_t)(row0 + (f >> 4)) * D_ +
                                 (f & 15) * 4);
    }
#pragma unroll
    for (int it = 0; it < 2; it++) {
        const int k = 2 * (bkp + it * 16);
        be[it][0] = bsrc0[(size_t)k * R_];
        be[it][1] = bsrc0[(size_t)(k + 1) * R_];
    }

    for (int t = 0; t < NSLAB; t++) {
        __syncthreads();  // previous slab's compute done
        // ---- stage x hi/lo (bf16 pairs, parity-XOR swizzle) ----
#pragma unroll
        for (int i = 0; i < 8; i++) {
            const int f = i * 256 + tid;
            const int r = f >> 4;
            const int kq = f & 15;
            const float4 v = xv[i];
            const uint32_t h0 = bfpack_hi(v.x, v.y);
            const uint32_t h1 = bfpack_hi(v.z, v.w);
            const uint32_t l0 =
                bfpack_rn(v.x - bflo_f(h0), v.y - bfhi_f(h0));
            const uint32_t l1 =
                bfpack_rn(v.z - bflo_f(h1), v.w - bfhi_f(h1));
            const int par = r & 1;
            const int base = r * XS_STR;
            xh[base + ((2 * kq) ^ par)] = h0;
            xh[base + ((2 * kq + 1) ^ par)] = h1;
            xl[base + ((2 * kq) ^ par)] = l0;
            xl[base + ((2 * kq + 1) ^ par)] = l1;
        }
        // ---- stage B hi/lo ----
#pragma unroll
        for (int it = 0; it < 2; it++) {
            const int kp = bkp + it * 16;
            const float e0 = be[it][0];
            const float e1 = be[it][1];
            const uint32_t h = bfpack_hi(e0, e1);
            const uint32_t l = bfpack_rn(e0 - bflo_f(h), e1 - bfhi_f(h));
            bh[kp * BS_STR + bn] = h;
            bl[kp * BS_STR + bn] = l;
        }
        __syncthreads();

        // ---- prefetch slab t+1 ----
        if (t + 1 < NSLAB) {
            const int kb = (t + 1) * KSLAB;
#pragma unroll
            for (int i = 0; i < 8; i++) {
                const int f = i * 256 + tid;
                xv[i] = *(const float4*)(x + (size_t)(row0 + (f >> 4)) * D_ +
                                         kb + (f & 15) * 4);
            }
#pragma unroll
            for (int it = 0; it < 2; it++) {
                const int k = kb + 2 * (bkp + it * 16);
                be[it][0] = bsrc0[(size_t)k * R_];
                be[it][1] = bsrc0[(size_t)(k + 1) * R_];
            }
        }

        // ---- compute: 4 k16-steps, 2 n-tiles, 3 passes ----
        const int r0 = w * 16 + g;
        const int par = g & 1;  // (w*16+g)&1 == g&1; row +8 same parity
        const uint32_t* xh0 = &xh[r0 * XS_STR];
        const uint32_t* xh1 = &xh[(r0 + 8) * XS_STR];
        const uint32_t* xl0 = &xl[r0 * XS_STR];
        const uint32_t* xl1 = &xl[(r0 + 8) * XS_STR];
#pragma unroll
        for (int ks = 0; ks < 4; ks++) {
            const int p0 = (ks * 8 + tg) ^ par;
            const int p1 = (ks * 8 + tg + 4) ^ par;
            const uint32_t ah0 = xh0[p0], ah1 = xh1[p0];
            const uint32_t ah2 = xh0[p1], ah3 = xh1[p1];
            const uint32_t al0 = xl0[p0], al1 = xl1[p0];
            const uint32_t al2 = xl0[p1], al3 = xl1[p1];
            const int q0 = ks * 8 + tg;
            const int q1 = q0 + 4;
#pragma unroll
            for (int nt = 0; nt < 2; nt++) {
                const int n0 = nt * 8 + g;
                const uint32_t bh0 = bh[q0 * BS_STR + n0];
                const uint32_t bh1 = bh[q1 * BS_STR + n0];
                mma_bf16(acc[nt], ah0, ah1, ah2, ah3, bh0, bh1);
                const uint32_t bl0 = bl[q0 * BS_STR + n0];
                const uint32_t bl1 = bl[q1 * BS_STR + n0];
                mma_bf16(acc[nt], ah0, ah1, ah2, ah3, bl0, bl1);
                mma_bf16(acc[nt], al0, al1, al2, al3, bh0, bh1);
            }
        }
    }

    // ---- store C frags: lane holds rows (g, g+8), cols nt*8 + 2tg..+1 ----
#pragma unroll
    for (int nt = 0; nt < 2; nt++) {
        const int col = nt * 8 + 2 * tg;
        float* o0 = g_h + (size_t)(row0 + w * 16 + g) * 16 + col;
        o0[0] = acc[nt][0];
        o0[1] = acc[nt][1];
        float* o1 = g_h + (size_t)(row0 + w * 16 + g + 8) * 16 + col;
        o1[0] = acc[nt][2];
        o1[1] = acc[nt][3];
    }
}

// ============================================================================
// Stage 2 (R9/R12 winner, verbatim): out = relu(0.25 * h @ Ac)
// ============================================================================
__global__ __launch_bounds__(S2_THREADS) void lora_stage2(
    const float* __restrict__ aa, float* __restrict__ out) {
    __shared__ float hsf[SROWS * 16];

    const int tid = threadIdx.x;
    const int b = blockIdx.z;
    const int s0 = blockIdx.x * SROWS;
    const size_t row0 = (size_t)b * S_ + s0;
    const int d0 = blockIdx.y * 1024 + tid * 4;

    {
        const float2* hp = (const float2*)g_h + row0 * 8;
#pragma unroll
        for (int g = 0; g < (SROWS * 8) / S2_THREADS; g++) {
            const int i = tid + g * S2_THREADS;
            float2 v = hp[i];
            hsf[2 * i + 0] = v.x * 0.25f;
            hsf[2 * i + 1] = v.y * 0.25f;
        }
    }
    __syncthreads();

    unsigned long long areg[16][2];
#pragma unroll
    for (int j = 0; j < 4; j++) {
#pragma unroll
        for (int r = 0; r < 4; r++) {
            float4 v = *(const float4*)(aa + (size_t)(4 * b + j) * (R_ * D_) +
                                        (size_t)r * D_ + d0);
            areg[j * 4 + r][0] = pack2(v.x, v.y);
            areg[j * 4 + r][1] = pack2(v.z, v.w);
        }
    }

    float* orow = out + row0 * D_ + d0;
    for (int rr = 0; rr < SROWS; rr++) {
        const float* hrow = &hsf[rr * 16];
        unsigned long long a0 = 0ull, a1 = 0ull, a2 = 0ull, a3 = 0ull;
#pragma unroll
        for (int c = 0; c < 16; c += 2) {
            const float h0 = hrow[c];
            const float h1 = hrow[c + 1];
            const unsigned long long hp0 = pack2(h0, h0);
            const unsigned long long hp1 = pack2(h1, h1);
            a0 = fma2(hp0, areg[c + 0][0], a0);
            a1 = fma2(hp0, areg[c + 0][1], a1);
            a2 = fma2(hp1, areg[c + 1][0], a2);
            a3 = fma2(hp1, areg[c + 1][1], a3);
        }
        const unsigned long long s01 = add2(a0, a2);
        const unsigned long long s23 = add2(a1, a3);
        float2 v0 = unpack2(s01);
        float2 v1 = unpack2(s23);
        float4 o;
        o.x = fmaxf(v0.x, 0.0f);
        o.y = fmaxf(v0.y, 0.0f);
        o.z = fmaxf(v1.x, 0.0f);
        o.w = fmaxf(v1.y, 0.0f);
        *(float4*)(orow + (size_t)rr * D_) = o;
    }
}

extern "C" void kernel_launch(void* const* d_in, const int* in_sizes, int n_in,
                              void* d_out, int out_size) {
    const float* x = (const float*)d_in[0];
    const float* ab = (const float*)d_in[1];
    const float* aa = (const float*)d_in[2];
    float* out = (float*)d_out;

    lora_stage1_mma<<<(B_ * S_) / TILE_M, S1_THREADS>>>(x, ab);

    dim3 g2(S_ / SROWS, D_ / 1024, B_);
    lora_stage2<<<g2, S2_THREADS>>>(aa, out);
}